// round 8
// baseline (speedup 1.0000x reference)
#include <cuda_runtime.h>

// linear_sig: depth-3 path signature (B=2048, T=128, C=8) + linear head (584 -> 10)
//
// R8: split-4 over T via Chen's identity. One row per 128-thread block; warp w
// signs increments [32w, 32w+32) (last one zero-padded), then a two-level
// combine tree: (0<-1, 2<-3) then (0<-2). Combine rule (A then B):
//   S1c = S1a + S1b
//   S2c[i,j]   = S2a + S2b + S1a[i] S1b[j]
//   S3c[i,j,l] = S3a + S3b + S2a[i,j] S1b[l] + S1a[i] S2b[j,l]
// Step body unchanged from R7 (8x fma.rn.f32x2 S3, 2 pack-MOVs, scalar aux).
// Rationale: R7 was warp-supply-bound (4096 warps = 43% occ ceiling, issue 42%).
// 8192 warps / 2048 blocks raises supply past the 64-reg 50% ceiling.

constexpr int TT      = 128;
constexpr int CC      = 8;
constexpr int NOUT    = 10;
constexpr int SIGDIM  = 584;      // 8 + 64 + 512
constexpr int WARPS   = 4;        // 4 segments of one row
constexpr int THREADS = WARPS * 32;   // 128
constexpr int STEPS   = 32;       // increments per segment
constexpr int W2SZ    = NOUT * 32 * 19;   // 6080
constexpr int SLOT    = 620;      // floats per state-dump slot (615 used)
constexpr int SMEMF   = 3 * SLOT; // 1860 floats (staging 1024 aliases into this)

__device__ float g_W2[W2SZ];      // reordered W, written by prep kernel

using ull = unsigned long long;

__device__ __forceinline__ ull dup2(float x) {
    ull r; asm("mov.b64 %0,{%1,%1};" : "=l"(r) : "f"(x)); return r;
}
__device__ __forceinline__ float2 upk(ull v) {
    float2 f; asm("mov.b64 {%0,%1},%2;" : "=f"(f.x), "=f"(f.y) : "l"(v)); return f;
}
__device__ __forceinline__ void f2fma(ull& acc, ull a, ull b) {
    asm("fma.rn.f32x2 %0,%1,%2,%0;" : "+l"(acc) : "l"(a), "l"(b));
}

// Reorder W once: g_W2[n*608 + r*19 + k]
//   k=0,1   -> W[n, 8 + 2r + k]            (S2 pair)
//   k=2..17 -> W[n, 72 + 16r + (k-2)]      (S3 block)
//   k=18    -> (r%4==0) ? W[n, r/4] : 0    (S1, dedup across replicas)
__global__ __launch_bounds__(256) void prep_w_kernel(const float* __restrict__ W) {
    int idx = blockIdx.x * blockDim.x + threadIdx.x;
    if (idx >= W2SZ) return;
    int n   = idx / (32 * 19);
    int rem = idx - n * (32 * 19);
    int r   = rem / 19;
    int k   = rem - r * 19;
    const float* Wn = W + n * SIGDIM;
    float v;
    if (k < 2)       v = Wn[8 + 2 * r + k];
    else if (k < 18) v = Wn[72 + 16 * r + (k - 2)];
    else             v = ((r & 3) == 0) ? Wn[r >> 2] : 0.0f;
    g_W2[idx] = v;
}

// Dump a lane-distributed state into slot cb.
__device__ __forceinline__ void dump_state(float* cb, int lane, int i0, int j0,
                                           float S1, float S20, float S21,
                                           const float* S3) {
    if ((lane & 3) == 0) cb[i0] = S1;
    cb[8 + i0 * 8 + j0]     = S20;
    cb[8 + i0 * 8 + j0 + 1] = S21;
    float* c3 = cb + 72 + lane * 17;
    #pragma unroll
    for (int k = 0; k < 16; k++) c3[k] = S3[k];
}

// In-place combine: (this state A) <- A then B, B read from slot cb.
__device__ __forceinline__ void combine_state(const float* cb, int i0, int j0, int lane,
                                              float& S1, float& S20, float& S21,
                                              float* S3) {
    const float* c3 = cb + 72 + lane * 17;
    #pragma unroll
    for (int l = 0; l < 8; l++) {
        float s1bl = cb[l];
        S3[l]     += c3[l]     + S20 * s1bl + S1 * cb[8 + j0 * 8 + l];
        S3[8 + l] += c3[8 + l] + S21 * s1bl + S1 * cb[8 + (j0 + 1) * 8 + l];
    }
    S20 += cb[8 + i0 * 8 + j0]     + S1 * cb[j0];
    S21 += cb[8 + i0 * 8 + j0 + 1] + S1 * cb[j0 + 1];
    S1  += cb[i0];
}

__global__ __launch_bounds__(THREADS, 8)
void sig_linear_kernel(const float* __restrict__ X,
                       const float* __restrict__ Bv,
                       float* __restrict__ out, int nB)
{
    __shared__ __align__(16) float smem[SMEMF];

    const int wib  = threadIdx.x >> 5;     // segment 0..3
    const int lane = threadIdx.x & 31;
    const int row  = blockIdx.x;
    const bool active = row < nB;

    const int i0 = lane >> 2;
    const int j0 = (lane & 3) << 1;
    const int t0 = wib * STEPS;

    float* sxw = smem + wib * (STEPS * CC);   // staging: 256 floats per segment

    // Stage dx one-shot: lane s handles increment t0+s (x[g+1]-x[g]); g=127 pads 0.
    if (active) {
        const float* xb = X + (size_t)row * (TT * CC);
        int g = t0 + lane;
        float4 da, db;
        if (g < TT - 1) {
            float4 a0 = *(const float4*)(xb + g * 8);
            float4 a1 = *(const float4*)(xb + g * 8 + 4);
            float4 b0 = *(const float4*)(xb + (g + 1) * 8);
            float4 b1 = *(const float4*)(xb + (g + 1) * 8 + 4);
            da = make_float4(b0.x - a0.x, b0.y - a0.y, b0.z - a0.z, b0.w - a0.w);
            db = make_float4(b1.x - a1.x, b1.y - a1.y, b1.z - a1.z, b1.w - a1.w);
        } else {
            da = make_float4(0.f, 0.f, 0.f, 0.f);
            db = da;
        }
        *(float4*)(sxw + lane * 8)     = da;
        *(float4*)(sxw + lane * 8 + 4) = db;
    }
    __syncwarp();

    float S1 = 0.f, S1h = 0.f;            // S1[i], S1[i]/2
    float S20 = 0.f, S21 = 0.f;
    ull S3p[8];                            // m<4: (S3[i,j0,2m], S3[i,j0,2m+1]); m>=4: j0+1
    #pragma unroll
    for (int m = 0; m < 8; m++) S3p[m] = 0ull;

    if (active) {
        #pragma unroll 4
        for (int s = 0; s < STEPS; s++) {
            const float* rw = sxw + s * 8;
            ulonglong2 qa = *(const ulonglong2*)(rw);      // (dx0,dx1),(dx2,dx3)
            ulonglong2 qb = *(const ulonglong2*)(rw + 4);  // (dx4,dx5),(dx6,dx7)
            float2 dxj = *(const float2*)(rw + j0);
            float  dxi = rw[i0];

            float u   = fmaf(dxi, 1.f / 6.f, S1h);         // OLD S1 baked in
            float v   = fmaf(dxi, 0.5f, S1);
            float t30 = fmaf(dxj.x, u, S20);               // OLD S2
            float t31 = fmaf(dxj.y, u, S21);
            ull T0 = dup2(t30);
            ull T1 = dup2(t31);

            f2fma(S3p[0], qa.x, T0);
            f2fma(S3p[1], qa.y, T0);
            f2fma(S3p[2], qb.x, T0);
            f2fma(S3p[3], qb.y, T0);
            f2fma(S3p[4], qa.x, T1);
            f2fma(S3p[5], qa.y, T1);
            f2fma(S3p[6], qb.x, T1);
            f2fma(S3p[7], qb.y, T1);

            S20 = fmaf(dxj.x, v, S20);
            S21 = fmaf(dxj.y, v, S21);
            S1 += dxi;
            S1h = fmaf(dxi, 0.5f, S1h);
        }
    }

    // Unpack S3 to scalar for the combine tree.
    float S3[16];
    #pragma unroll
    for (int m = 0; m < 8; m++) {
        float2 f = upk(S3p[m]);
        S3[2 * m] = f.x; S3[2 * m + 1] = f.y;
    }

    __syncthreads();   // staging reads done -> smem reusable as dump slots

    // Slots: A = seg1 dump, B = seg3 dump, C = (2+3) combined dump
    float* slotA = smem;
    float* slotB = smem + SLOT;
    float* slotC = smem + 2 * SLOT;

    if (active && wib == 1) dump_state(slotA, lane, i0, j0, S1, S20, S21, S3);
    if (active && wib == 3) dump_state(slotB, lane, i0, j0, S1, S20, S21, S3);
    __syncthreads();

    if (active && wib == 0) combine_state(slotA, i0, j0, lane, S1, S20, S21, S3);
    if (active && wib == 2) {
        combine_state(slotB, i0, j0, lane, S1, S20, S21, S3);
        dump_state(slotC, lane, i0, j0, S1, S20, S21, S3);
    }
    __syncthreads();

    if (active && wib == 0) {
        combine_state(slotC, i0, j0, lane, S1, S20, S21, S3);

        // Epilogue: out[row, n] = b[n] + <sig, W[n]>  (reordered W from L2)
        float* orow = out + (size_t)row * NOUT;
        #pragma unroll
        for (int n = 0; n < NOUT; n++) {
            const float* wn = g_W2 + n * (32 * 19) + lane * 19;
            float p = S20 * __ldg(wn) + S21 * __ldg(wn + 1) + S1 * __ldg(wn + 18);
            #pragma unroll
            for (int k = 0; k < 16; k++) p += S3[k] * __ldg(wn + 2 + k);
            #pragma unroll
            for (int off = 16; off; off >>= 1)
                p += __shfl_xor_sync(0xffffffffu, p, off);
            if (lane == 0) orow[n] = p + __ldg(Bv + n);
        }
    }
}

extern "C" void kernel_launch(void* const* d_in, const int* in_sizes, int n_in,
                              void* d_out, int out_size) {
    const float* X  = (const float*)d_in[0];
    const float* W  = (const float*)d_in[1];
    const float* b  = (const float*)d_in[2];
    float* out      = (float*)d_out;
    int nB = in_sizes[0] / (TT * CC);                 // 2048
    prep_w_kernel<<<(W2SZ + 255) / 256, 256>>>(W);
    sig_linear_kernel<<<nB, THREADS>>>(X, b, out, nB);   // 2048 blocks, 1 row each
}

// round 10
// speedup vs baseline: 1.0957x; 1.0957x over previous
#include <cuda_runtime.h>

// linear_sig: depth-3 path signature (B=2048, T=128, C=8) + linear head (584 -> 10)
//
// R10 = R9 resubmit (R9 bench failed on infra, theory untested).
// R7 (best, split-2 over T via Chen) with two tail optimizations:
//  1. prep kernel removed: epilogue gathers W directly with mapped indices
//     (vectorized float2/float4 loads, L2-hot), single kernel launch.
//  2. epilogue parallelized 4x: combiner dumps final state to smem (S3 at
//     stride 20 -> aligned LDS.128), then each of the 4 warps computes 5 of
//     the 20 (pair,n) dot products.
// Mainloop unchanged: 8x fma.rn.f32x2 S3 update, 2 pack-MOVs, scalar aux;
// lane r owns i=r>>2, j in {2(r&3), 2(r&3)+1}. Chen combine (A then B):
//   S1c = S1a + S1b
//   S2c[i,j]   = S2a + S2b + S1a[i] S1b[j]
//   S3c[i,j,l] = S3a + S3b + S2a[i,j] S1b[l] + S1a[i] S2b[j,l]

constexpr int TT      = 128;
constexpr int CC      = 8;
constexpr int NOUT    = 10;
constexpr int SIGDIM  = 584;      // 8 + 64 + 512
constexpr int WARPS   = 4;        // 2 row-pairs per block
constexpr int PAIRS   = WARPS / 2;
constexpr int THREADS = WARPS * 32;   // 128
constexpr int STEPS   = 64;       // increments per half

using ull = unsigned long long;

__device__ __forceinline__ ull dup2(float x) {
    ull r; asm("mov.b64 %0,{%1,%1};" : "=l"(r) : "f"(x)); return r;
}
__device__ __forceinline__ float2 upk(ull v) {
    float2 f; asm("mov.b64 {%0,%1},%2;" : "=f"(f.x), "=f"(f.y) : "l"(v)); return f;
}
__device__ __forceinline__ void f2fma(ull& acc, ull a, ull b) {
    asm("fma.rn.f32x2 %0,%1,%2,%0;" : "+l"(acc) : "l"(a), "l"(b));
}

// State slot layout (712 floats): [0..7]=S1, [8..71]=S2, [72 + r*20 + k]=S3[r][k]
__device__ __forceinline__ void dump20(float* f, int lane, int i0, int j0,
                                       float S1, float S20, float S21,
                                       const float* S3) {
    if ((lane & 3) == 0) f[i0] = S1;
    *(float2*)(f + 8 + i0 * 8 + j0) = make_float2(S20, S21);
    float* c3 = f + 72 + lane * 20;
    *(float4*)(c3)      = make_float4(S3[0],  S3[1],  S3[2],  S3[3]);
    *(float4*)(c3 + 4)  = make_float4(S3[4],  S3[5],  S3[6],  S3[7]);
    *(float4*)(c3 + 8)  = make_float4(S3[8],  S3[9],  S3[10], S3[11]);
    *(float4*)(c3 + 12) = make_float4(S3[12], S3[13], S3[14], S3[15]);
}

// In-place: (state A) <- A then B, B read from slot f.
__device__ __forceinline__ void combine20(const float* f, int i0, int j0, int lane,
                                          float& S1, float& S20, float& S21,
                                          float* S3) {
    const float* c3 = f + 72 + lane * 20;
    #pragma unroll
    for (int l = 0; l < 8; l++) {
        float s1bl = f[l];
        S3[l]     += c3[l]     + S20 * s1bl + S1 * f[8 + j0 * 8 + l];
        S3[8 + l] += c3[8 + l] + S21 * s1bl + S1 * f[8 + (j0 + 1) * 8 + l];
    }
    S20 += f[8 + i0 * 8 + j0]     + S1 * f[j0];
    S21 += f[8 + i0 * 8 + j0 + 1] + S1 * f[j0 + 1];
    S1  += f[i0];
}

__global__ __launch_bounds__(THREADS, 8)
void sig_linear_kernel(const float* __restrict__ X,
                       const float* __restrict__ W,
                       const float* __restrict__ Bv,
                       float* __restrict__ out, int nB)
{
    __shared__ __align__(16) float sx[PAIRS][2][STEPS * CC];  // staging; aliased as state slots

    const int wib  = threadIdx.x >> 5;
    const int lane = threadIdx.x & 31;
    const int pair = wib >> 1;
    const int half = wib & 1;                  // 0 = combiner
    const int row  = blockIdx.x * PAIRS + pair;
    const bool active = row < nB;

    const int i0 = lane >> 2;
    const int j0 = (lane & 3) << 1;
    const int t0 = half ? STEPS : 0;

    float* sxw = &sx[pair][half][0];

    // Stage dx: slot s holds x[t0+s+1]-x[t0+s]; global index 127 pads to 0.
    if (active) {
        const float* xb = X + (size_t)row * (TT * CC);
        #pragma unroll
        for (int s = lane; s < STEPS; s += 32) {
            int g = t0 + s;
            float4 da, db;
            if (g < TT - 1) {
                float4 a0 = *(const float4*)(xb + g * 8);
                float4 a1 = *(const float4*)(xb + g * 8 + 4);
                float4 b0 = *(const float4*)(xb + (g + 1) * 8);
                float4 b1 = *(const float4*)(xb + (g + 1) * 8 + 4);
                da = make_float4(b0.x - a0.x, b0.y - a0.y, b0.z - a0.z, b0.w - a0.w);
                db = make_float4(b1.x - a1.x, b1.y - a1.y, b1.z - a1.z, b1.w - a1.w);
            } else {
                da = make_float4(0.f, 0.f, 0.f, 0.f);
                db = da;
            }
            *(float4*)(sxw + s * 8)     = da;
            *(float4*)(sxw + s * 8 + 4) = db;
        }
    }
    __syncwarp();

    float S1 = 0.f, S1h = 0.f;            // S1[i], S1[i]/2
    float S20 = 0.f, S21 = 0.f;
    ull S3p[8];
    #pragma unroll
    for (int m = 0; m < 8; m++) S3p[m] = 0ull;

    if (active) {
        #pragma unroll 4
        for (int s = 0; s < STEPS; s++) {
            const float* rw = sxw + s * 8;
            ulonglong2 qa = *(const ulonglong2*)(rw);      // (dx0,dx1),(dx2,dx3)
            ulonglong2 qb = *(const ulonglong2*)(rw + 4);  // (dx4,dx5),(dx6,dx7)
            float2 dxj = *(const float2*)(rw + j0);
            float  dxi = rw[i0];

            float u   = fmaf(dxi, 1.f / 6.f, S1h);         // OLD S1 baked in
            float v   = fmaf(dxi, 0.5f, S1);
            float t30 = fmaf(dxj.x, u, S20);               // OLD S2
            float t31 = fmaf(dxj.y, u, S21);
            ull T0 = dup2(t30);
            ull T1 = dup2(t31);

            f2fma(S3p[0], qa.x, T0);
            f2fma(S3p[1], qa.y, T0);
            f2fma(S3p[2], qb.x, T0);
            f2fma(S3p[3], qb.y, T0);
            f2fma(S3p[4], qa.x, T1);
            f2fma(S3p[5], qa.y, T1);
            f2fma(S3p[6], qb.x, T1);
            f2fma(S3p[7], qb.y, T1);

            S20 = fmaf(dxj.x, v, S20);
            S21 = fmaf(dxj.y, v, S21);
            S1 += dxi;
            S1h = fmaf(dxi, 0.5f, S1h);
        }
    }

    float S3[16];
    #pragma unroll
    for (int m = 0; m < 8; m++) {
        float2 f = upk(S3p[m]);
        S3[2 * m] = f.x; S3[2 * m + 1] = f.y;
    }

    __syncthreads();   // staging reads done -> smem reusable as state slots

    float* fslot = &sx[pair][0][0];   // 712 of the pair's 1024 staging floats

    if (active && half == 1) dump20(fslot, lane, i0, j0, S1, S20, S21, S3);
    __syncthreads();

    if (active && half == 0) {
        combine20(fslot, i0, j0, lane, S1, S20, S21, S3);
        __syncwarp();                  // all combine reads done before overwrite
        dump20(fslot, lane, i0, j0, S1, S20, S21, S3);
    }
    __syncthreads();

    // Parallel epilogue: warp w -> pair (w>>1), outputs n in [ (w&1)*5, +5 ).
    {
        const int p    = wib >> 1;
        const int rowE = blockIdx.x * PAIRS + p;
        if (rowE < nB) {
            const float* f = &sx[p][0][0];
            float s1  = f[i0];
            float2 s2 = *(const float2*)(f + 8 + i0 * 8 + j0);
            const float* c3 = f + 72 + lane * 20;
            float4 a0 = *(const float4*)(c3);
            float4 a1 = *(const float4*)(c3 + 4);
            float4 a2 = *(const float4*)(c3 + 8);
            float4 a3 = *(const float4*)(c3 + 12);

            float* orow = out + (size_t)rowE * NOUT;
            const int n0 = (wib & 1) * 5;
            #pragma unroll
            for (int q = 0; q < 5; q++) {
                int n = n0 + q;
                const float* wn = W + n * SIGDIM;
                float2 w2 = *(const float2*)(wn + 8 + 2 * lane);
                const float* w3 = wn + 72 + 16 * lane;
                float4 b0 = *(const float4*)(w3);
                float4 b1 = *(const float4*)(w3 + 4);
                float4 b2 = *(const float4*)(w3 + 8);
                float4 b3 = *(const float4*)(w3 + 12);
                float w1 = ((lane & 3) == 0) ? wn[lane >> 2] : 0.f;

                float pa = s2.x * w2.x + s2.y * w2.y + s1 * w1;
                pa += a0.x * b0.x + a0.y * b0.y + a0.z * b0.z + a0.w * b0.w;
                pa += a1.x * b1.x + a1.y * b1.y + a1.z * b1.z + a1.w * b1.w;
                pa += a2.x * b2.x + a2.y * b2.y + a2.z * b2.z + a2.w * b2.w;
                pa += a3.x * b3.x + a3.y * b3.y + a3.z * b3.z + a3.w * b3.w;
                #pragma unroll
                for (int off = 16; off; off >>= 1)
                    pa += __shfl_xor_sync(0xffffffffu, pa, off);
                if (lane == 0) orow[n] = pa + Bv[n];
            }
        }
    }
}

extern "C" void kernel_launch(void* const* d_in, const int* in_sizes, int n_in,
                              void* d_out, int out_size) {
    const float* X  = (const float*)d_in[0];
    const float* W  = (const float*)d_in[1];
    const float* b  = (const float*)d_in[2];
    float* out      = (float*)d_out;
    int nB = in_sizes[0] / (TT * CC);                 // 2048
    int grid = (nB + PAIRS - 1) / PAIRS;              // 1024 blocks
    sig_linear_kernel<<<grid, THREADS>>>(X, W, b, out, nB);
}

// round 11
// speedup vs baseline: 1.2304x; 1.1229x over previous
#include <cuda_runtime.h>

// linear_sig: depth-3 path signature (B=2048, T=128, C=8) + linear head (584 -> 10)
//
// R11 = R10 with a coalesced epilogue. R10's epilogue read W lane-scattered
// (64B lane stride -> 16 sector-wavefronts per LDG.128), spiking L1 to 72%.
// Now: each warp loads its pair's signature once as 19 lane-parallel smem
// values (linear sig idx -> slot offset = idx + 4*((idx-72)>>4) for S3), then
// per output n does 19 coalesced LDG.32 from W[n, 32q+lane] + FMA + shuffle
// reduce. Mainloop/combine unchanged from R10 (split-2 via Chen, 8x
// fma.rn.f32x2 S3 step).

constexpr int TT      = 128;
constexpr int CC      = 8;
constexpr int NOUT    = 10;
constexpr int SIGDIM  = 584;      // 8 + 64 + 512
constexpr int WARPS   = 4;        // 2 row-pairs per block
constexpr int PAIRS   = WARPS / 2;
constexpr int THREADS = WARPS * 32;   // 128
constexpr int STEPS   = 64;       // increments per half
constexpr int NQ      = 19;       // ceil(584/32)

using ull = unsigned long long;

__device__ __forceinline__ ull dup2(float x) {
    ull r; asm("mov.b64 %0,{%1,%1};" : "=l"(r) : "f"(x)); return r;
}
__device__ __forceinline__ float2 upk(ull v) {
    float2 f; asm("mov.b64 {%0,%1},%2;" : "=f"(f.x), "=f"(f.y) : "l"(v)); return f;
}
__device__ __forceinline__ void f2fma(ull& acc, ull a, ull b) {
    asm("fma.rn.f32x2 %0,%1,%2,%0;" : "+l"(acc) : "l"(a), "l"(b));
}

// State slot layout (712 floats): [0..7]=S1, [8..71]=S2(i*8+j), [72+r*20+k]=S3[r][k]
// Linear sig index idx maps to slot offset: idx<72 -> idx; else idx + 4*((idx-72)>>4).
__device__ __forceinline__ void dump20(float* f, int lane, int i0, int j0,
                                       float S1, float S20, float S21,
                                       const float* S3) {
    if ((lane & 3) == 0) f[i0] = S1;
    *(float2*)(f + 8 + i0 * 8 + j0) = make_float2(S20, S21);
    float* c3 = f + 72 + lane * 20;
    *(float4*)(c3)      = make_float4(S3[0],  S3[1],  S3[2],  S3[3]);
    *(float4*)(c3 + 4)  = make_float4(S3[4],  S3[5],  S3[6],  S3[7]);
    *(float4*)(c3 + 8)  = make_float4(S3[8],  S3[9],  S3[10], S3[11]);
    *(float4*)(c3 + 12) = make_float4(S3[12], S3[13], S3[14], S3[15]);
}

// In-place: (state A) <- A then B, B read from slot f.
__device__ __forceinline__ void combine20(const float* f, int i0, int j0, int lane,
                                          float& S1, float& S20, float& S21,
                                          float* S3) {
    const float* c3 = f + 72 + lane * 20;
    #pragma unroll
    for (int l = 0; l < 8; l++) {
        float s1bl = f[l];
        S3[l]     += c3[l]     + S20 * s1bl + S1 * f[8 + j0 * 8 + l];
        S3[8 + l] += c3[8 + l] + S21 * s1bl + S1 * f[8 + (j0 + 1) * 8 + l];
    }
    S20 += f[8 + i0 * 8 + j0]     + S1 * f[j0];
    S21 += f[8 + i0 * 8 + j0 + 1] + S1 * f[j0 + 1];
    S1  += f[i0];
}

__global__ __launch_bounds__(THREADS, 8)
void sig_linear_kernel(const float* __restrict__ X,
                       const float* __restrict__ W,
                       const float* __restrict__ Bv,
                       float* __restrict__ out, int nB)
{
    __shared__ __align__(16) float sx[PAIRS][2][STEPS * CC];  // staging; aliased as state slots

    const int wib  = threadIdx.x >> 5;
    const int lane = threadIdx.x & 31;
    const int pair = wib >> 1;
    const int half = wib & 1;                  // 0 = combiner
    const int row  = blockIdx.x * PAIRS + pair;
    const bool active = row < nB;

    const int i0 = lane >> 2;
    const int j0 = (lane & 3) << 1;
    const int t0 = half ? STEPS : 0;

    float* sxw = &sx[pair][half][0];

    // Stage dx: slot s holds x[t0+s+1]-x[t0+s]; global index 127 pads to 0.
    if (active) {
        const float* xb = X + (size_t)row * (TT * CC);
        #pragma unroll
        for (int s = lane; s < STEPS; s += 32) {
            int g = t0 + s;
            float4 da, db;
            if (g < TT - 1) {
                float4 a0 = *(const float4*)(xb + g * 8);
                float4 a1 = *(const float4*)(xb + g * 8 + 4);
                float4 b0 = *(const float4*)(xb + (g + 1) * 8);
                float4 b1 = *(const float4*)(xb + (g + 1) * 8 + 4);
                da = make_float4(b0.x - a0.x, b0.y - a0.y, b0.z - a0.z, b0.w - a0.w);
                db = make_float4(b1.x - a1.x, b1.y - a1.y, b1.z - a1.z, b1.w - a1.w);
            } else {
                da = make_float4(0.f, 0.f, 0.f, 0.f);
                db = da;
            }
            *(float4*)(sxw + s * 8)     = da;
            *(float4*)(sxw + s * 8 + 4) = db;
        }
    }
    __syncwarp();

    float S1 = 0.f, S1h = 0.f;            // S1[i], S1[i]/2
    float S20 = 0.f, S21 = 0.f;
    ull S3p[8];
    #pragma unroll
    for (int m = 0; m < 8; m++) S3p[m] = 0ull;

    if (active) {
        #pragma unroll 4
        for (int s = 0; s < STEPS; s++) {
            const float* rw = sxw + s * 8;
            ulonglong2 qa = *(const ulonglong2*)(rw);      // (dx0,dx1),(dx2,dx3)
            ulonglong2 qb = *(const ulonglong2*)(rw + 4);  // (dx4,dx5),(dx6,dx7)
            float2 dxj = *(const float2*)(rw + j0);
            float  dxi = rw[i0];

            float u   = fmaf(dxi, 1.f / 6.f, S1h);         // OLD S1 baked in
            float v   = fmaf(dxi, 0.5f, S1);
            float t30 = fmaf(dxj.x, u, S20);               // OLD S2
            float t31 = fmaf(dxj.y, u, S21);
            ull T0 = dup2(t30);
            ull T1 = dup2(t31);

            f2fma(S3p[0], qa.x, T0);
            f2fma(S3p[1], qa.y, T0);
            f2fma(S3p[2], qb.x, T0);
            f2fma(S3p[3], qb.y, T0);
            f2fma(S3p[4], qa.x, T1);
            f2fma(S3p[5], qa.y, T1);
            f2fma(S3p[6], qb.x, T1);
            f2fma(S3p[7], qb.y, T1);

            S20 = fmaf(dxj.x, v, S20);
            S21 = fmaf(dxj.y, v, S21);
            S1 += dxi;
            S1h = fmaf(dxi, 0.5f, S1h);
        }
    }

    float S3[16];
    #pragma unroll
    for (int m = 0; m < 8; m++) {
        float2 f = upk(S3p[m]);
        S3[2 * m] = f.x; S3[2 * m + 1] = f.y;
    }

    __syncthreads();   // staging reads done -> smem reusable as state slots

    float* fslot = &sx[pair][0][0];   // 712 of the pair's 1024 staging floats

    if (active && half == 1) dump20(fslot, lane, i0, j0, S1, S20, S21, S3);
    __syncthreads();

    if (active && half == 0) {
        combine20(fslot, i0, j0, lane, S1, S20, S21, S3);
        __syncwarp();                  // all combine reads done before overwrite
        dump20(fslot, lane, i0, j0, S1, S20, S21, S3);
    }
    __syncthreads();

    // Coalesced epilogue: warp w -> pair (w>>1), outputs n in [(w&1)*5, +5).
    // Lane holds sig[32q+lane] for q=0..18 (loaded once); W read coalesced.
    {
        const int p    = wib >> 1;
        const int rowE = blockIdx.x * PAIRS + p;
        if (rowE < nB) {
            const float* f = &sx[p][0][0];
            float sv[NQ];
            #pragma unroll
            for (int q = 0; q < NQ; q++) {
                int idx = q * 32 + lane;
                if (idx < SIGDIM) {
                    int off = (idx < 72) ? idx : idx + (((idx - 72) >> 4) << 2);
                    sv[q] = f[off];
                } else {
                    sv[q] = 0.f;
                }
            }

            float* orow = out + (size_t)rowE * NOUT;
            const int n0 = (wib & 1) * 5;
            for (int q5 = 0; q5 < 5; q5++) {
                int n = n0 + q5;
                const float* wr = W + (size_t)n * SIGDIM;
                float pa = 0.f;
                #pragma unroll
                for (int q = 0; q < NQ - 1; q++)
                    pa = fmaf(sv[q], wr[q * 32 + lane], pa);   // coalesced LDG.32
                {
                    int idx = (NQ - 1) * 32 + lane;
                    float wv = (idx < SIGDIM) ? wr[idx] : 0.f;
                    pa = fmaf(sv[NQ - 1], wv, pa);
                }
                #pragma unroll
                for (int off = 16; off; off >>= 1)
                    pa += __shfl_xor_sync(0xffffffffu, pa, off);
                if (lane == 0) orow[n] = pa + Bv[n];
            }
        }
    }
}

extern "C" void kernel_launch(void* const* d_in, const int* in_sizes, int n_in,
                              void* d_out, int out_size) {
    const float* X  = (const float*)d_in[0];
    const float* W  = (const float*)d_in[1];
    const float* b  = (const float*)d_in[2];
    float* out      = (float*)d_out;
    int nB = in_sizes[0] / (TT * CC);                 // 2048
    int grid = (nB + PAIRS - 1) / PAIRS;              // 1024 blocks
    sig_linear_kernel<<<grid, THREADS>>>(X, W, b, out, nB);
}

// round 12
// speedup vs baseline: 1.2325x; 1.0017x over previous
#include <cuda_runtime.h>

// linear_sig: depth-3 path signature (B=2048, T=128, C=8) + linear head (584 -> 10)
//
// R12 = R11 + explicit software pipelining of the mainloop (prefetch step s+1's
// LDS loads while computing step s; wrap index avoids OOB), branchless dx
// staging (clamped g+1 makes the pad increment naturally zero), active-guards
// removed (grid divides exactly). Structure otherwise identical to R11:
// split-2 over T via Chen, 8x fma.rn.f32x2 S3 step, stride-20 state dump,
// 4x-parallel coalesced epilogue.

constexpr int TT      = 128;
constexpr int CC      = 8;
constexpr int NOUT    = 10;
constexpr int SIGDIM  = 584;      // 8 + 64 + 512
constexpr int WARPS   = 4;        // 2 row-pairs per block
constexpr int PAIRS   = WARPS / 2;
constexpr int THREADS = WARPS * 32;   // 128
constexpr int STEPS   = 64;       // increments per half
constexpr int NQ      = 19;       // ceil(584/32)

using ull = unsigned long long;

__device__ __forceinline__ ull dup2(float x) {
    ull r; asm("mov.b64 %0,{%1,%1};" : "=l"(r) : "f"(x)); return r;
}
__device__ __forceinline__ float2 upk(ull v) {
    float2 f; asm("mov.b64 {%0,%1},%2;" : "=f"(f.x), "=f"(f.y) : "l"(v)); return f;
}
__device__ __forceinline__ void f2fma(ull& acc, ull a, ull b) {
    asm("fma.rn.f32x2 %0,%1,%2,%0;" : "+l"(acc) : "l"(a), "l"(b));
}

// State slot layout (712 floats): [0..7]=S1, [8..71]=S2(i*8+j), [72+r*20+k]=S3[r][k]
// Linear sig index idx maps to slot offset: idx<72 -> idx; else idx + 4*((idx-72)>>4).
__device__ __forceinline__ void dump20(float* f, int lane, int i0, int j0,
                                       float S1, float S20, float S21,
                                       const float* S3) {
    if ((lane & 3) == 0) f[i0] = S1;
    *(float2*)(f + 8 + i0 * 8 + j0) = make_float2(S20, S21);
    float* c3 = f + 72 + lane * 20;
    *(float4*)(c3)      = make_float4(S3[0],  S3[1],  S3[2],  S3[3]);
    *(float4*)(c3 + 4)  = make_float4(S3[4],  S3[5],  S3[6],  S3[7]);
    *(float4*)(c3 + 8)  = make_float4(S3[8],  S3[9],  S3[10], S3[11]);
    *(float4*)(c3 + 12) = make_float4(S3[12], S3[13], S3[14], S3[15]);
}

// In-place: (state A) <- A then B, B read from slot f.
__device__ __forceinline__ void combine20(const float* f, int i0, int j0, int lane,
                                          float& S1, float& S20, float& S21,
                                          float* S3) {
    const float* c3 = f + 72 + lane * 20;
    #pragma unroll
    for (int l = 0; l < 8; l++) {
        float s1bl = f[l];
        S3[l]     += c3[l]     + S20 * s1bl + S1 * f[8 + j0 * 8 + l];
        S3[8 + l] += c3[8 + l] + S21 * s1bl + S1 * f[8 + (j0 + 1) * 8 + l];
    }
    S20 += f[8 + i0 * 8 + j0]     + S1 * f[j0];
    S21 += f[8 + i0 * 8 + j0 + 1] + S1 * f[j0 + 1];
    S1  += f[i0];
}

__global__ __launch_bounds__(THREADS, 8)
void sig_linear_kernel(const float* __restrict__ X,
                       const float* __restrict__ W,
                       const float* __restrict__ Bv,
                       float* __restrict__ out, int nB)
{
    __shared__ __align__(16) float sx[PAIRS][2][STEPS * CC];  // staging; aliased as state slots

    const int wib  = threadIdx.x >> 5;
    const int lane = threadIdx.x & 31;
    const int pair = wib >> 1;
    const int half = wib & 1;                  // 0 = combiner
    const int row  = blockIdx.x * PAIRS + pair;

    const int i0 = lane >> 2;
    const int j0 = (lane & 3) << 1;
    const int t0 = half ? STEPS : 0;

    float* sxw = &sx[pair][half][0];

    // Stage dx (branchless): slot s holds x[min(g+1,127)]-x[g]; pad slot -> 0.
    {
        const float* xb = X + (size_t)row * (TT * CC);
        #pragma unroll
        for (int s = lane; s < STEPS; s += 32) {
            int g  = t0 + s;
            int g1 = (g + 1 < TT - 1) ? g + 1 : TT - 1;
            float4 a0 = *(const float4*)(xb + g * 8);
            float4 a1 = *(const float4*)(xb + g * 8 + 4);
            float4 b0 = *(const float4*)(xb + g1 * 8);
            float4 b1 = *(const float4*)(xb + g1 * 8 + 4);
            *(float4*)(sxw + s * 8)     = make_float4(b0.x - a0.x, b0.y - a0.y,
                                                      b0.z - a0.z, b0.w - a0.w);
            *(float4*)(sxw + s * 8 + 4) = make_float4(b1.x - a1.x, b1.y - a1.y,
                                                      b1.z - a1.z, b1.w - a1.w);
        }
    }
    __syncwarp();

    float S1 = 0.f, S1h = 0.f;            // S1[i], S1[i]/2
    float S20 = 0.f, S21 = 0.f;
    ull S3p[8];
    #pragma unroll
    for (int m = 0; m < 8; m++) S3p[m] = 0ull;

    {
        // Software pipeline: current step's operands in registers, prefetch s+1.
        ulonglong2 qa = *(const ulonglong2*)(sxw);
        ulonglong2 qb = *(const ulonglong2*)(sxw + 4);
        float2 dj = *(const float2*)(sxw + j0);
        float  di = sxw[i0];

        #pragma unroll 4
        for (int s = 0; s < STEPS; s++) {
            const float* rn = sxw + ((s + 1) & (STEPS - 1)) * 8;  // s=63 wraps (dummy)
            ulonglong2 qa_n = *(const ulonglong2*)(rn);
            ulonglong2 qb_n = *(const ulonglong2*)(rn + 4);
            float2 dj_n = *(const float2*)(rn + j0);
            float  di_n = rn[i0];

            float u   = fmaf(di, 1.f / 6.f, S1h);          // OLD S1 baked in
            float v   = fmaf(di, 0.5f, S1);
            float t30 = fmaf(dj.x, u, S20);                // OLD S2
            float t31 = fmaf(dj.y, u, S21);
            ull T0 = dup2(t30);
            ull T1 = dup2(t31);

            f2fma(S3p[0], qa.x, T0);
            f2fma(S3p[1], qa.y, T0);
            f2fma(S3p[2], qb.x, T0);
            f2fma(S3p[3], qb.y, T0);
            f2fma(S3p[4], qa.x, T1);
            f2fma(S3p[5], qa.y, T1);
            f2fma(S3p[6], qb.x, T1);
            f2fma(S3p[7], qb.y, T1);

            S20 = fmaf(dj.x, v, S20);
            S21 = fmaf(dj.y, v, S21);
            S1 += di;
            S1h = fmaf(di, 0.5f, S1h);

            qa = qa_n; qb = qb_n; dj = dj_n; di = di_n;
        }
    }

    float S3[16];
    #pragma unroll
    for (int m = 0; m < 8; m++) {
        float2 f = upk(S3p[m]);
        S3[2 * m] = f.x; S3[2 * m + 1] = f.y;
    }

    __syncthreads();   // staging reads done -> smem reusable as state slots

    float* fslot = &sx[pair][0][0];   // 712 of the pair's 1024 staging floats

    if (half == 1) dump20(fslot, lane, i0, j0, S1, S20, S21, S3);
    __syncthreads();

    if (half == 0) {
        combine20(fslot, i0, j0, lane, S1, S20, S21, S3);
        __syncwarp();                  // all combine reads done before overwrite
        dump20(fslot, lane, i0, j0, S1, S20, S21, S3);
    }
    __syncthreads();

    // Coalesced epilogue: warp w -> pair (w>>1), outputs n in [(w&1)*5, +5).
    // Lane holds sig[32q+lane] for q=0..18 (loaded once); W read coalesced.
    {
        const int p    = wib >> 1;
        const int rowE = blockIdx.x * PAIRS + p;
        const float* f = &sx[p][0][0];
        float sv[NQ];
        #pragma unroll
        for (int q = 0; q < NQ; q++) {
            int idx = q * 32 + lane;
            if (idx < SIGDIM) {
                int off = (idx < 72) ? idx : idx + (((idx - 72) >> 4) << 2);
                sv[q] = f[off];
            } else {
                sv[q] = 0.f;
            }
        }

        float* orow = out + (size_t)rowE * NOUT;
        const int n0 = (wib & 1) * 5;
        for (int q5 = 0; q5 < 5; q5++) {
            int n = n0 + q5;
            const float* wr = W + (size_t)n * SIGDIM;
            float pa = 0.f;
            #pragma unroll
            for (int q = 0; q < NQ - 1; q++)
                pa = fmaf(sv[q], wr[q * 32 + lane], pa);   // coalesced LDG.32
            {
                int idx = (NQ - 1) * 32 + lane;
                float wv = (idx < SIGDIM) ? wr[idx] : 0.f;
                pa = fmaf(sv[NQ - 1], wv, pa);
            }
            #pragma unroll
            for (int off = 16; off; off >>= 1)
                pa += __shfl_xor_sync(0xffffffffu, pa, off);
            if (lane == 0) orow[n] = pa + Bv[n];
        }
    }
}

extern "C" void kernel_launch(void* const* d_in, const int* in_sizes, int n_in,
                              void* d_out, int out_size) {
    const float* X  = (const float*)d_in[0];
    const float* W  = (const float*)d_in[1];
    const float* b  = (const float*)d_in[2];
    float* out      = (float*)d_out;
    int nB = in_sizes[0] / (TT * CC);                 // 2048
    int grid = (nB + PAIRS - 1) / PAIRS;              // 1024 blocks
    sig_linear_kernel<<<grid, THREADS>>>(X, W, b, out, nB);
}